// round 2
// baseline (speedup 1.0000x reference)
#include <cuda_runtime.h>
#include <cstdint>

#define BATCH 8
#define SEQ   2048
#define EMBD  1024

// ---- scratch (no allocations allowed; __device__ globals are the sanctioned path) ----
__device__ float g_Q [(size_t)BATCH*SEQ*EMBD];
__device__ float g_K [(size_t)BATCH*SEQ*EMBD];
__device__ float g_V [(size_t)BATCH*SEQ*EMBD];
__device__ float g_Vt[(size_t)BATCH*EMBD*SEQ];
__device__ float g_rowsum[BATCH*SEQ];

__device__ __forceinline__ uint32_t f2tf32(float x){
  uint32_t u; asm("cvt.rna.tf32.f32 %0, %1;" : "=r"(u) : "f"(x)); return u;
}
__device__ __forceinline__ void cp16(void* sm, const void* gm){
  uint32_t s = (uint32_t)__cvta_generic_to_shared(sm);
  asm volatile("cp.async.cg.shared.global [%0], [%1], 16;" :: "r"(s), "l"(gm));
}

// ============================================================================
// Unified tf32 GEMM:  C[m][n] = sum_k A[m][k] * B[n][k]   (both K-major, "nt")
// MODE 0: proj       C += bias[n]
// MODE 1: scores     C = mask ? 0 : exp(scale*acc); atomicAdd row sums
// MODE 2: out        C = acc / rowsum[row]
// Tiling: CTA 128x128x16, 256 threads, 8 warps (2x4), warp tile 64x32.
// ============================================================================
template<int MODE>
__global__ __launch_bounds__(256)
void gemm_tf32(const float* __restrict__ Ag, const float* __restrict__ Bg,
               float* __restrict__ Cg,
               const float* __restrict__ bias,
               const int*   __restrict__ maskg,
               float* __restrict__ rowsum,
               int M, int N, int Kd,
               long batchA, long batchB, long batchC, long batchMask, int batchRS,
               float scale)
{
  const int b = blockIdx.z;
  const float* A = Ag + (long)b*batchA;
  const float* B = Bg + (long)b*batchB;
  float*       C = Cg + (long)b*batchC;

  const int m0 = blockIdx.y * 128;
  const int n0 = blockIdx.x * 128;

  __shared__ float As[2][128][20];
  __shared__ float Bs[2][128][20];

  const int tid  = threadIdx.x;
  const int lane = tid & 31;
  const int warp = tid >> 5;
  const int wm = warp >> 2;   // 0..1
  const int wn = warp & 3;    // 0..3
  const int g  = lane >> 2;   // 0..7
  const int t  = lane & 3;    // 0..3

  float c[4][4][4];
  #pragma unroll
  for (int i=0;i<4;i++)
    #pragma unroll
    for (int j=0;j<4;j++)
      #pragma unroll
      for (int q=0;q<4;q++) c[i][j][q] = 0.f;

  const int NT = Kd >> 4;   // K tiles of 16

  // tile loader: 512 float4 per operand tile, 2 per thread
  auto load_tiles = [&](int kt, int buf){
    const int k0 = kt << 4;
    #pragma unroll
    for (int r=0;r<2;r++){
      int idx = tid + (r<<8);
      int row = idx >> 2;
      int c4  = idx & 3;
      cp16(&As[buf][row][c4*4], A + (long)(m0+row)*Kd + k0 + c4*4);
      cp16(&Bs[buf][row][c4*4], B + (long)(n0+row)*Kd + k0 + c4*4);
    }
    asm volatile("cp.async.commit_group;");
  };

  load_tiles(0, 0);
  for (int kt=0; kt<NT; kt++){
    const int cur = kt & 1;
    if (kt+1 < NT) load_tiles(kt+1, cur^1);
    else           asm volatile("cp.async.commit_group;");
    asm volatile("cp.async.wait_group 1;");
    __syncthreads();

    #pragma unroll
    for (int kk=0; kk<16; kk+=8){
      uint32_t af[4][4], bf[4][2];
      #pragma unroll
      for (int mt=0; mt<4; mt++){
        const int rb = wm*64 + mt*16;
        af[mt][0] = f2tf32(As[cur][rb+g  ][kk+t  ]);
        af[mt][1] = f2tf32(As[cur][rb+g+8][kk+t  ]);
        af[mt][2] = f2tf32(As[cur][rb+g  ][kk+t+4]);
        af[mt][3] = f2tf32(As[cur][rb+g+8][kk+t+4]);
      }
      #pragma unroll
      for (int nt=0; nt<4; nt++){
        const int nb = wn*32 + nt*8;
        bf[nt][0] = f2tf32(Bs[cur][nb+g][kk+t  ]);
        bf[nt][1] = f2tf32(Bs[cur][nb+g][kk+t+4]);
      }
      #pragma unroll
      for (int mt=0; mt<4; mt++)
        #pragma unroll
        for (int nt=0; nt<4; nt++){
          asm volatile(
            "mma.sync.aligned.m16n8k8.row.col.f32.tf32.tf32.f32 "
            "{%0,%1,%2,%3}, {%4,%5,%6,%7}, {%8,%9}, {%0,%1,%2,%3};"
            : "+f"(c[mt][nt][0]), "+f"(c[mt][nt][1]),
              "+f"(c[mt][nt][2]), "+f"(c[mt][nt][3])
            : "r"(af[mt][0]), "r"(af[mt][1]), "r"(af[mt][2]), "r"(af[mt][3]),
              "r"(bf[nt][0]), "r"(bf[nt][1]));
        }
    }
    __syncthreads();
  }

  // ---------------- epilogues ----------------
  if constexpr (MODE == 0){
    #pragma unroll
    for (int mt=0; mt<4; mt++){
      const int r0 = m0 + wm*64 + mt*16 + g;
      #pragma unroll
      for (int nt=0; nt<4; nt++){
        const int cc = n0 + wn*32 + nt*8 + 2*t;
        const float b0 = bias[cc], b1 = bias[cc+1];
        *reinterpret_cast<float2*>(&C[(long)r0*N + cc])     = make_float2(c[mt][nt][0]+b0, c[mt][nt][1]+b1);
        *reinterpret_cast<float2*>(&C[(long)(r0+8)*N + cc]) = make_float2(c[mt][nt][2]+b0, c[mt][nt][3]+b1);
      }
    }
  } else if constexpr (MODE == 1){
    const int* Mk = maskg + (long)b*batchMask;
    float rs0[4] = {0,0,0,0}, rs1[4] = {0,0,0,0};
    #pragma unroll
    for (int mt=0; mt<4; mt++){
      const int r0 = m0 + wm*64 + mt*16 + g;
      #pragma unroll
      for (int nt=0; nt<4; nt++){
        const int cc = n0 + wn*32 + nt*8 + 2*t;
        const long i0 = (long)r0*N + cc;
        const long i1 = (long)(r0+8)*N + cc;
        float e0 = Mk[i0  ] ? 0.f : __expf(c[mt][nt][0]*scale);
        float e1 = Mk[i0+1] ? 0.f : __expf(c[mt][nt][1]*scale);
        float e2 = Mk[i1  ] ? 0.f : __expf(c[mt][nt][2]*scale);
        float e3 = Mk[i1+1] ? 0.f : __expf(c[mt][nt][3]*scale);
        *reinterpret_cast<float2*>(&C[i0]) = make_float2(e0, e1);
        *reinterpret_cast<float2*>(&C[i1]) = make_float2(e2, e3);
        rs0[mt] += e0 + e1;
        rs1[mt] += e2 + e3;
      }
    }
    #pragma unroll
    for (int mt=0; mt<4; mt++){
      float s0 = rs0[mt], s1 = rs1[mt];
      s0 += __shfl_xor_sync(0xffffffffu, s0, 1);
      s0 += __shfl_xor_sync(0xffffffffu, s0, 2);
      s1 += __shfl_xor_sync(0xffffffffu, s1, 1);
      s1 += __shfl_xor_sync(0xffffffffu, s1, 2);
      if (t == 0){
        const int r0 = m0 + wm*64 + mt*16 + g;
        atomicAdd(&rowsum[b*batchRS + r0    ], s0);
        atomicAdd(&rowsum[b*batchRS + r0 + 8], s1);
      }
    }
  } else { // MODE 2
    #pragma unroll
    for (int mt=0; mt<4; mt++){
      const int r0 = m0 + wm*64 + mt*16 + g;
      const float inv0 = 1.0f / rowsum[b*batchRS + r0    ];
      const float inv1 = 1.0f / rowsum[b*batchRS + r0 + 8];
      #pragma unroll
      for (int nt=0; nt<4; nt++){
        const int cc = n0 + wn*32 + nt*8 + 2*t;
        *reinterpret_cast<float2*>(&C[(long)r0*N + cc])     = make_float2(c[mt][nt][0]*inv0, c[mt][nt][1]*inv0);
        *reinterpret_cast<float2*>(&C[(long)(r0+8)*N + cc]) = make_float2(c[mt][nt][2]*inv1, c[mt][nt][3]*inv1);
      }
    }
  }
}

// V [b][SEQ][EMBD] -> Vt [b][EMBD][SEQ]
__global__ void transpose_v(const float* __restrict__ src, float* __restrict__ dst){
  __shared__ float tile[32][33];
  const int b  = blockIdx.z;
  const int j0 = blockIdx.y * 32;  // seq
  const int k0 = blockIdx.x * 32;  // emb
  const float* s = src + (long)b*SEQ*EMBD;
  float*       d = dst + (long)b*EMBD*SEQ;
  const int x = threadIdx.x, y = threadIdx.y;
  #pragma unroll
  for (int r=0; r<32; r+=8)
    tile[y+r][x] = s[(long)(j0+y+r)*EMBD + k0 + x];
  __syncthreads();
  #pragma unroll
  for (int r=0; r<32; r+=8)
    d[(long)(k0+y+r)*SEQ + j0 + x] = tile[x][y+r];
}

__global__ void init_zero(float* p){
  p[blockIdx.x*1024 + threadIdx.x] = 0.f;
}

// att (raw exp) -> normalized, in place; row = b*SEQ + i, 512 float4 per row
__global__ void norm_att(float* __restrict__ att, const float* __restrict__ rowsum){
  const long gid = (long)blockIdx.x*blockDim.x + threadIdx.x;
  const long row = gid >> 9;
  const float inv = 1.0f / rowsum[row];
  float4 v = reinterpret_cast<float4*>(att)[gid];
  v.x *= inv; v.y *= inv; v.z *= inv; v.w *= inv;
  reinterpret_cast<float4*>(att)[gid] = v;
}

extern "C" void kernel_launch(void* const* d_in, const int* in_sizes, int n_in,
                              void* d_out, int out_size)
{
  const float* x   = (const float*)d_in[0];
  const float* ctx = (const float*)d_in[1];
  const int*   msk = (const int*)  d_in[2];
  const float* Wq  = (const float*)d_in[3];
  const float* bq  = (const float*)d_in[4];
  const float* Wk  = (const float*)d_in[5];
  const float* bk  = (const float*)d_in[6];
  const float* Wv  = (const float*)d_in[7];
  const float* bv  = (const float*)d_in[8];

  float* out = (float*)d_out;                           // [8][2048][1024]
  float* att = out + (size_t)BATCH*SEQ*EMBD;            // [8][2048][2048]

  float *qp, *kp, *vp, *vtp, *rsp;
  cudaGetSymbolAddress((void**)&qp,  g_Q);
  cudaGetSymbolAddress((void**)&kp,  g_K);
  cudaGetSymbolAddress((void**)&vp,  g_V);
  cudaGetSymbolAddress((void**)&vtp, g_Vt);
  cudaGetSymbolAddress((void**)&rsp, g_rowsum);

  init_zero<<<16, 1024>>>(rsp);

  const dim3 blk(256);
  // QKV projections: C[16384,1024] = A[16384,1024] . W[1024,1024]^T + bias
  gemm_tf32<0><<<dim3(EMBD/128, (BATCH*SEQ)/128, 1), blk>>>(
      x,   Wq, qp, bq, nullptr, nullptr, BATCH*SEQ, EMBD, EMBD, 0,0,0,0,0, 1.f);
  gemm_tf32<0><<<dim3(EMBD/128, (BATCH*SEQ)/128, 1), blk>>>(
      ctx, Wk, kp, bk, nullptr, nullptr, BATCH*SEQ, EMBD, EMBD, 0,0,0,0,0, 1.f);
  gemm_tf32<0><<<dim3(EMBD/128, (BATCH*SEQ)/128, 1), blk>>>(
      ctx, Wv, vp, bv, nullptr, nullptr, BATCH*SEQ, EMBD, EMBD, 0,0,0,0,0, 1.f);

  transpose_v<<<dim3(EMBD/32, SEQ/32, BATCH), dim3(32,8)>>>(vp, vtp);

  // scores: att = exp(mask? -inf : Q.K^T * 1/32), partial row sums via atomics
  gemm_tf32<1><<<dim3(SEQ/128, SEQ/128, BATCH), blk>>>(
      qp, kp, att, nullptr, msk, rsp, SEQ, SEQ, EMBD,
      (long)SEQ*EMBD, (long)SEQ*EMBD, (long)SEQ*SEQ, (long)SEQ*SEQ, SEQ, 0.03125f);

  // out = (raw_exp . Vt^T) / rowsum   (reads att BEFORE normalization; stream-ordered)
  gemm_tf32<2><<<dim3(EMBD/128, SEQ/128, BATCH), blk>>>(
      att, vtp, out, nullptr, nullptr, rsp, SEQ, EMBD, SEQ,
      (long)SEQ*SEQ, (long)EMBD*SEQ, (long)SEQ*EMBD, 0, SEQ, 1.f);

  // finalize att in place
  norm_att<<<(int)(((long)BATCH*SEQ*SEQ/4)/256), 256>>>(att, rsp);
}

// round 4
// speedup vs baseline: 1.1687x; 1.1687x over previous
#include <cuda_runtime.h>
#include <cstdint>

#define BATCH 8
#define SEQ   2048
#define EMBD  1024

// ---- scratch (__device__ globals; allocation is forbidden) ----
__device__ float g_Q [(size_t)BATCH*SEQ*EMBD];
__device__ float g_K [(size_t)BATCH*SEQ*EMBD];
__device__ float g_V [(size_t)BATCH*SEQ*EMBD];
__device__ float g_Vt[(size_t)BATCH*EMBD*SEQ];
__device__ float g_Xr[(size_t)BATCH*SEQ*EMBD];   // tf32-rounded x
__device__ float g_Cr[(size_t)BATCH*SEQ*EMBD];   // tf32-rounded context
__device__ float g_Wr[3*(size_t)EMBD*EMBD];      // tf32-rounded Wq|Wk|Wv
__device__ float g_rowsum[BATCH*SEQ];

__device__ __forceinline__ float f2tf32(float x){
  uint32_t u; asm("cvt.rna.tf32.f32 %0, %1;" : "=r"(u) : "f"(x));
  return __uint_as_float(u);
}
__device__ __forceinline__ void cp16(void* sm, const void* gm){
  uint32_t s = (uint32_t)__cvta_generic_to_shared(sm);
  asm volatile("cp.async.cg.shared.global [%0], [%1], 16;" :: "r"(s), "l"(gm));
}
__device__ __forceinline__ void ldsm4(uint32_t& r0,uint32_t& r1,uint32_t& r2,uint32_t& r3,
                                      const float* p){
  uint32_t s = (uint32_t)__cvta_generic_to_shared(p);
  asm volatile("ldmatrix.sync.aligned.m8n8.x4.shared.b16 {%0,%1,%2,%3}, [%4];"
    : "=r"(r0),"=r"(r1),"=r"(r2),"=r"(r3) : "r"(s));
}

// elementwise tf32 rounding pass (float4 vectorized, n % 1024 == 0)
__global__ void round_copy(const float* __restrict__ src, float* __restrict__ dst){
  const long i = (long)blockIdx.x*blockDim.x + threadIdx.x;
  float4 v = reinterpret_cast<const float4*>(src)[i];
  v.x = f2tf32(v.x); v.y = f2tf32(v.y); v.z = f2tf32(v.z); v.w = f2tf32(v.w);
  reinterpret_cast<float4*>(dst)[i] = v;
}

// ============================================================================
// tf32 GEMM:  C[m][n] = sum_k A[m][k] * B[n][k]   (nt, operands pre-rounded)
// MODE 0: proj    C = round(acc + bias[n])        (Q/K/V kept tf32-exact)
// MODE 1: scores  C = mask ? 0 : round(exp(scale*acc)); atomicAdd row sums
// MODE 2: out     C = acc / rowsum[row]           (full precision output)
// CTA 128x128x32, 256 thr, 8 warps (2x4), warp 64x32, ldmatrix fragments.
// ============================================================================
#define SM_STRIDE 36
#define AS(st,r,c) sA[((st)*128 + (r))*SM_STRIDE + (c)]
#define BS(st,r,c) sB[((st)*128 + (r))*SM_STRIDE + (c)]

template<int MODE>
__global__ __launch_bounds__(256, 2)
void gemm_tf32(const float* __restrict__ Ag, const float* __restrict__ Bg,
               float* __restrict__ Cg,
               const float* __restrict__ bias,
               const int*   __restrict__ maskg,
               float* __restrict__ rowsum,
               int N, int Kd,
               long batchA, long batchB, long batchC, long batchMask, int batchRS,
               float scale)
{
  extern __shared__ float smem[];
  float* sA = smem;                      // [2][128][36]
  float* sB = smem + 2*128*SM_STRIDE;    // [2][128][36]

  const int b = blockIdx.z;
  const float* A = Ag + (long)b*batchA;
  const float* B = Bg + (long)b*batchB;
  float*       C = Cg + (long)b*batchC;

  const int m0 = blockIdx.y * 128;
  const int n0 = blockIdx.x * 128;

  const int tid  = threadIdx.x;
  const int lane = tid & 31;
  const int warp = tid >> 5;
  const int wm = warp >> 2;   // 0..1
  const int wn = warp & 3;    // 0..3
  const int g  = lane >> 2;   // 0..7
  const int t  = lane & 3;    // 0..3

  // ldmatrix per-lane source coordinates
  const int aR = lane & 15;             // row within 16-row A tile
  const int aC = (lane & 16) >> 2;      // +4 col for upper half
  const int bR = (lane & 7) + ((lane & 16) >> 1);  // row within 16-row B pair
  const int bC = (lane & 8) >> 1;       // +4 col

  float c[4][4][4];
  #pragma unroll
  for (int i=0;i<4;i++)
    #pragma unroll
    for (int j=0;j<4;j++){ c[i][j][0]=0.f;c[i][j][1]=0.f;c[i][j][2]=0.f;c[i][j][3]=0.f; }

  const int NT = Kd >> 5;   // K tiles of 32

  auto load_tiles = [&](int kt, int buf){
    const int k0 = kt << 5;
    #pragma unroll
    for (int r=0;r<4;r++){
      int idx = tid + (r<<8);           // 0..1023
      int row = idx >> 3;
      int c4  = (idx & 7) << 2;
      cp16(&AS(buf,row,c4), A + (long)(m0+row)*Kd + k0 + c4);
      cp16(&BS(buf,row,c4), B + (long)(n0+row)*Kd + k0 + c4);
    }
    asm volatile("cp.async.commit_group;");
  };

  load_tiles(0, 0);
  for (int kt=0; kt<NT; kt++){
    const int cur = kt & 1;
    if (kt+1 < NT) load_tiles(kt+1, cur^1);
    else           asm volatile("cp.async.commit_group;");
    asm volatile("cp.async.wait_group 1;");
    __syncthreads();

    #pragma unroll
    for (int kk=0; kk<32; kk+=8){
      uint32_t af[4][4], bf[4][2];
      #pragma unroll
      for (int mt=0; mt<4; mt++)
        ldsm4(af[mt][0], af[mt][1], af[mt][2], af[mt][3],
              &AS(cur, wm*64 + mt*16 + aR, kk + aC));
      #pragma unroll
      for (int np=0; np<2; np++)
        ldsm4(bf[2*np][0], bf[2*np][1], bf[2*np+1][0], bf[2*np+1][1],
              &BS(cur, wn*32 + np*16 + bR, kk + bC));
      #pragma unroll
      for (int mt=0; mt<4; mt++)
        #pragma unroll
        for (int nt=0; nt<4; nt++){
          asm volatile(
            "mma.sync.aligned.m16n8k8.row.col.f32.tf32.tf32.f32 "
            "{%0,%1,%2,%3}, {%4,%5,%6,%7}, {%8,%9}, {%0,%1,%2,%3};"
            : "+f"(c[mt][nt][0]), "+f"(c[mt][nt][1]),
              "+f"(c[mt][nt][2]), "+f"(c[mt][nt][3])
            : "r"(af[mt][0]), "r"(af[mt][1]), "r"(af[mt][2]), "r"(af[mt][3]),
              "r"(bf[nt][0]), "r"(bf[nt][1]));
        }
    }
    __syncthreads();
  }

  // ---------------- epilogues ----------------
  if constexpr (MODE == 0){
    #pragma unroll
    for (int mt=0; mt<4; mt++){
      const int r0 = m0 + wm*64 + mt*16 + g;
      #pragma unroll
      for (int nt=0; nt<4; nt++){
        const int cc = n0 + wn*32 + nt*8 + 2*t;
        const float b0 = bias[cc], b1 = bias[cc+1];
        *reinterpret_cast<float2*>(&C[(long)r0*N + cc]) =
            make_float2(f2tf32(c[mt][nt][0]+b0), f2tf32(c[mt][nt][1]+b1));
        *reinterpret_cast<float2*>(&C[(long)(r0+8)*N + cc]) =
            make_float2(f2tf32(c[mt][nt][2]+b0), f2tf32(c[mt][nt][3]+b1));
      }
    }
  } else if constexpr (MODE == 1){
    const int* Mk = maskg + (long)b*batchMask;
    float rs0[4] = {0,0,0,0}, rs1[4] = {0,0,0,0};
    #pragma unroll
    for (int mt=0; mt<4; mt++){
      const int r0 = m0 + wm*64 + mt*16 + g;
      #pragma unroll
      for (int nt=0; nt<4; nt++){
        const int cc = n0 + wn*32 + nt*8 + 2*t;
        const long i0 = (long)r0*N + cc;
        const long i1 = (long)(r0+8)*N + cc;
        float e0 = Mk[i0  ] ? 0.f : f2tf32(__expf(c[mt][nt][0]*scale));
        float e1 = Mk[i0+1] ? 0.f : f2tf32(__expf(c[mt][nt][1]*scale));
        float e2 = Mk[i1  ] ? 0.f : f2tf32(__expf(c[mt][nt][2]*scale));
        float e3 = Mk[i1+1] ? 0.f : f2tf32(__expf(c[mt][nt][3]*scale));
        *reinterpret_cast<float2*>(&C[i0]) = make_float2(e0, e1);
        *reinterpret_cast<float2*>(&C[i1]) = make_float2(e2, e3);
        rs0[mt] += e0 + e1;
        rs1[mt] += e2 + e3;
      }
    }
    #pragma unroll
    for (int mt=0; mt<4; mt++){
      float s0 = rs0[mt], s1 = rs1[mt];
      s0 += __shfl_xor_sync(0xffffffffu, s0, 1);
      s0 += __shfl_xor_sync(0xffffffffu, s0, 2);
      s1 += __shfl_xor_sync(0xffffffffu, s1, 1);
      s1 += __shfl_xor_sync(0xffffffffu, s1, 2);
      if (t == 0){
        const int r0 = m0 + wm*64 + mt*16 + g;
        atomicAdd(&rowsum[b*batchRS + r0    ], s0);
        atomicAdd(&rowsum[b*batchRS + r0 + 8], s1);
      }
    }
  } else { // MODE 2
    #pragma unroll
    for (int mt=0; mt<4; mt++){
      const int r0 = m0 + wm*64 + mt*16 + g;
      const float inv0 = 1.0f / rowsum[b*batchRS + r0    ];
      const float inv1 = 1.0f / rowsum[b*batchRS + r0 + 8];
      #pragma unroll
      for (int nt=0; nt<4; nt++){
        const int cc = n0 + wn*32 + nt*8 + 2*t;
        *reinterpret_cast<float2*>(&C[(long)r0*N + cc])     = make_float2(c[mt][nt][0]*inv0, c[mt][nt][1]*inv0);
        *reinterpret_cast<float2*>(&C[(long)(r0+8)*N + cc]) = make_float2(c[mt][nt][2]*inv1, c[mt][nt][3]*inv1);
      }
    }
  }
}

// V [b][SEQ][EMBD] -> Vt [b][EMBD][SEQ]  (V already tf32-rounded at write)
__global__ void transpose_v(const float* __restrict__ src, float* __restrict__ dst){
  __shared__ float tile[32][33];
  const int b  = blockIdx.z;
  const int j0 = blockIdx.y * 32;
  const int k0 = blockIdx.x * 32;
  const float* s = src + (long)b*SEQ*EMBD;
  float*       d = dst + (long)b*EMBD*SEQ;
  const int x = threadIdx.x, y = threadIdx.y;
  #pragma unroll
  for (int r=0; r<32; r+=8)
    tile[y+r][x] = s[(long)(j0+y+r)*EMBD + k0 + x];
  __syncthreads();
  #pragma unroll
  for (int r=0; r<32; r+=8)
    d[(long)(k0+y+r)*SEQ + j0 + x] = tile[x][y+r];
}

__global__ void init_zero(float* p){
  p[blockIdx.x*1024 + threadIdx.x] = 0.f;
}

// att (raw rounded exp) -> normalized, in place
__global__ void norm_att(float* __restrict__ att, const float* __restrict__ rowsum){
  const long gid = (long)blockIdx.x*blockDim.x + threadIdx.x;
  const long row = gid >> 9;
  const float inv = 1.0f / rowsum[row];
  float4 v = reinterpret_cast<float4*>(att)[gid];
  v.x *= inv; v.y *= inv; v.z *= inv; v.w *= inv;
  reinterpret_cast<float4*>(att)[gid] = v;
}

extern "C" void kernel_launch(void* const* d_in, const int* in_sizes, int n_in,
                              void* d_out, int out_size)
{
  const float* x   = (const float*)d_in[0];
  const float* ctx = (const float*)d_in[1];
  const int*   msk = (const int*)  d_in[2];
  const float* Wq  = (const float*)d_in[3];
  const float* bq  = (const float*)d_in[4];
  const float* Wk  = (const float*)d_in[5];
  const float* bk  = (const float*)d_in[6];
  const float* Wv  = (const float*)d_in[7];
  const float* bv  = (const float*)d_in[8];

  float* out = (float*)d_out;                   // [8][2048][1024]
  float* att = out + (size_t)BATCH*SEQ*EMBD;    // [8][2048][2048]

  float *qp, *kp, *vp, *vtp, *rsp, *xr, *cr, *wr;
  cudaGetSymbolAddress((void**)&qp,  g_Q);
  cudaGetSymbolAddress((void**)&kp,  g_K);
  cudaGetSymbolAddress((void**)&vp,  g_V);
  cudaGetSymbolAddress((void**)&vtp, g_Vt);
  cudaGetSymbolAddress((void**)&rsp, g_rowsum);
  cudaGetSymbolAddress((void**)&xr,  g_Xr);
  cudaGetSymbolAddress((void**)&cr,  g_Cr);
  cudaGetSymbolAddress((void**)&wr,  g_Wr);

  const int SMEM = 2*2*128*SM_STRIDE*4;   // 73728 B
  cudaFuncSetAttribute(gemm_tf32<0>, cudaFuncAttributeMaxDynamicSharedMemorySize, SMEM);
  cudaFuncSetAttribute(gemm_tf32<1>, cudaFuncAttributeMaxDynamicSharedMemorySize, SMEM);
  cudaFuncSetAttribute(gemm_tf32<2>, cudaFuncAttributeMaxDynamicSharedMemorySize, SMEM);

  init_zero<<<16, 1024>>>(rsp);

  // pre-round operands to tf32 (removes all in-loop cvt)
  round_copy<<<(int)((size_t)BATCH*SEQ*EMBD/4/256), 256>>>(x,   xr);
  round_copy<<<(int)((size_t)BATCH*SEQ*EMBD/4/256), 256>>>(ctx, cr);
  round_copy<<<EMBD*EMBD/4/256, 256>>>(Wq, wr);
  round_copy<<<EMBD*EMBD/4/256, 256>>>(Wk, wr +   (size_t)EMBD*EMBD);
  round_copy<<<EMBD*EMBD/4/256, 256>>>(Wv, wr + 2*(size_t)EMBD*EMBD);

  const dim3 blk(256);
  // QKV projections
  gemm_tf32<0><<<dim3(EMBD/128, (BATCH*SEQ)/128, 1), blk, SMEM>>>(
      xr, wr,                      qp, bq, nullptr, nullptr, EMBD, EMBD, 0,0,0,0,0, 1.f);
  gemm_tf32<0><<<dim3(EMBD/128, (BATCH*SEQ)/128, 1), blk, SMEM>>>(
      cr, wr + (size_t)EMBD*EMBD,  kp, bk, nullptr, nullptr, EMBD, EMBD, 0,0,0,0,0, 1.f);
  gemm_tf32<0><<<dim3(EMBD/128, (BATCH*SEQ)/128, 1), blk, SMEM>>>(
      cr, wr + 2*(size_t)EMBD*EMBD, vp, bv, nullptr, nullptr, EMBD, EMBD, 0,0,0,0,0, 1.f);

  transpose_v<<<dim3(EMBD/32, SEQ/32, BATCH), dim3(32,8)>>>(vp, vtp);

  // scores: att = round(exp(mask? -inf : Q.K^T/32)), partial row sums
  gemm_tf32<1><<<dim3(SEQ/128, SEQ/128, BATCH), blk, SMEM>>>(
      qp, kp, att, nullptr, msk, rsp, SEQ, EMBD,
      (long)SEQ*EMBD, (long)SEQ*EMBD, (long)SEQ*SEQ, (long)SEQ*SEQ, SEQ, 0.03125f);

  // out = (raw_exp . Vt^T) / rowsum  (reads att pre-normalization; stream-ordered)
  gemm_tf32<2><<<dim3(EMBD/128, SEQ/128, BATCH), blk, SMEM>>>(
      att, vtp, out, nullptr, nullptr, rsp, EMBD, SEQ,
      (long)SEQ*SEQ, (long)EMBD*SEQ, (long)SEQ*EMBD, 0, SEQ, 1.f);

  // finalize att in place
  norm_att<<<(int)(((long)BATCH*SEQ*SEQ/4)/256), 256>>>(att, rsp);
}